// round 12
// baseline (speedup 1.0000x reference)
#include <cuda_runtime.h>
#include <cstdint>

#define SEQ 128
#define BATCH 256
#define N_IN 1024
#define N_ST 256

// ---------------- static device scratch (no allocations allowed) ----------------
__device__ uint32_t g_inp[SEQ * BATCH * 8];     // packed input bits: [t][b][8 words]
__device__ uint32_t g_memA[N_IN * 2048];        // packed input-layer RAM: [n][2048 words]
__device__ uint32_t g_memB[N_ST * 2048];        // packed state-layer RAM
__device__ uint32_t g_connA[N_IN * 16];         // (shift<<16) | (row_word_offset)
__device__ uint32_t g_connB[N_ST * 16];

// Pack 32 float32 {0.0,1.0} elements -> one 32-bit word (bit j = elem j != 0).
__global__ void pack_f32_kernel(const float* __restrict__ src,
                                uint32_t* __restrict__ dst, int nwords) {
    int i = blockIdx.x * blockDim.x + threadIdx.x;
    if (i >= nwords) return;
    const uint4* q = (const uint4*)(src + (size_t)i * 32);
    uint32_t r = 0;
#pragma unroll
    for (int j = 0; j < 8; ++j) {
        uint4 x = q[j];
        r |= (x.x ? 1u : 0u) << (j * 4 + 0);
        r |= (x.y ? 1u : 0u) << (j * 4 + 1);
        r |= (x.z ? 1u : 0u) << (j * 4 + 2);
        r |= (x.w ? 1u : 0u) << (j * 4 + 3);
    }
    dst[i] = r;
}

// Unified layout U (48 rows x 32 lanes): rows 0-7 inp, 8-15 state, 16-47 io.
// connA positions p in [0,512): [inp|state] -> row = p>>5 directly.
__global__ void pack_connA_kernel(const int* __restrict__ conn,
                                  uint32_t* __restrict__ dst, int n) {
    int i = blockIdx.x * blockDim.x + threadIdx.x;
    if (i >= n) return;
    uint32_t v = (uint32_t)conn[i];
    dst[i] = ((v & 31u) << 16) | ((v >> 5) * 32u);
}

// connB positions p in [0,1280): [io(1024)|state(256)]
//   p < 1024 -> io row 16 + (p>>5);  p >= 1024 -> state row (p>>5) - 24.
__global__ void pack_connB_kernel(const int* __restrict__ conn,
                                  uint32_t* __restrict__ dst, int n) {
    int i = blockIdx.x * blockDim.x + threadIdx.x;
    if (i >= n) return;
    uint32_t v = (uint32_t)conn[i];
    uint32_t row = (v < 1024u) ? (16u + (v >> 5)) : ((v >> 5) - 24u);
    dst[i] = ((v & 31u) << 16) | (row * 32u);
}

// ---------------- main recurrent kernel ----------------
__device__ __forceinline__ uint32_t gstep(uint32_t a, uint32_t c,
                                          const uint32_t* __restrict__ rep, int lane) {
    uint32_t w = rep[(c & 0xffffu) + lane];
    return (a + a) | ((w >> (c >> 16)) & 1u);
}

__device__ __forceinline__ uint32_t gather16(const uint32_t* __restrict__ cw,
                                             const uint32_t* __restrict__ rep, int lane) {
    uint32_t a = 0;
#pragma unroll
    for (int k = 15; k >= 0; --k) a = gstep(a, cw[k], rep, lane);
    return a;
}

__device__ __forceinline__ float bit2f(uint32_t bit) {
    return __uint_as_float(0x3F800000u & (0u - bit));   // 1.0f / 0.0f, pure ALU
}

__global__ __launch_bounds__(256, 2)
void ram_main(const float* __restrict__ init_state, float* __restrict__ out) {
    // Ping-ponged lane-replicated bit vectors (bank == lane -> conflict-free).
    __shared__ uint32_t U[2][48 * 32];

    const int tid  = threadIdx.x;
    const int lane = tid & 31;
    const int w    = tid >> 5;          // warp 0..7
    const int b    = blockIdx.x;        // one batch per block

    // Hoist loop-invariant connections into registers (64 + 16 words).
    uint32_t cA[64], cB[16];
#pragma unroll
    for (int gi = 0; gi < 4; ++gi) {
        int n = (w * 4 + gi) * 32 + lane;
#pragma unroll
        for (int k = 0; k < 16; ++k) cA[gi * 16 + k] = g_connA[n * 16 + k];
    }
    {
        int m = w * 32 + lane;
#pragma unroll
        for (int k = 0; k < 16; ++k) cB[k] = g_connB[m * 16 + k];
    }

    // Pre-load step 0: init state + input into copy 0.
    {
        float f = init_state[b * N_ST + w * 32 + lane];
        uint32_t word = __ballot_sync(0xffffffffu, f != 0.0f);
        U[0][(8 + w) * 32 + lane] = word;
        U[0][w * 32 + lane] = __ldg(&g_inp[((size_t)0 * BATCH + b) * 8 + w]);
    }

    for (int t = 0; t < SEQ; ++t) {
        uint32_t* cur = U[t & 1];
        uint32_t* nxt = U[(t + 1) & 1];

        __syncthreads();   // prev step's state install + prefetched input visible

        // Prefetch next step's input (goes into the OTHER copy; nobody reads
        // nxt rows 0-7 during this step, so no barrier needed before the STS).
        uint32_t pin = 0;
        if (t + 1 < SEQ) pin = __ldg(&g_inp[((size_t)(t + 1) * BATCH + b) * 8 + w]);

        // ---- phase A: 1024 neurons; warp w handles groups w*4 .. w*4+3 ----
        // Interleave gather -> table LDG so each lookup issues ASAP (MLP early).
        float* outrow = out + ((size_t)t * BATCH + b) * N_IN;
        uint32_t acc[4], tw[4];
#pragma unroll
        for (int gi = 0; gi < 4; ++gi) {
            acc[gi] = gather16(&cA[gi * 16], cur, lane);
            int n = (w * 4 + gi) * 32 + lane;
            tw[gi] = __ldcg(&g_memA[n * 2048 + (acc[gi] >> 5)]);
        }

        if (t + 1 < SEQ) nxt[w * 32 + lane] = pin;   // hidden behind table LDGs

#pragma unroll
        for (int gi = 0; gi < 4; ++gi) {
            int g = w * 4 + gi;
            uint32_t bit = (tw[gi] >> (acc[gi] & 31u)) & 1u;
            uint32_t iow = __ballot_sync(0xffffffffu, bit != 0u);
            cur[(16 + g) * 32 + lane] = iow;          // replicate io word
            outrow[g * 32 + lane] = bit2f(bit);       // coalesced 128B store
        }
        __syncthreads();   // io words visible

        // ---- phase B: 256 neurons; warp w handles neurons w*32 .. w*32+31 ----
        int m = w * 32 + lane;
        uint32_t a   = gather16(cB, cur, lane);
        uint32_t twb = __ldcg(&g_memB[m * 2048 + (a >> 5)]);
        uint32_t bit = (twb >> (a & 31u)) & 1u;
        uint32_t sw2 = __ballot_sync(0xffffffffu, bit != 0u);

        if (t == SEQ - 1) {
            out[(size_t)SEQ * BATCH * N_IN + b * N_ST + m] = bit2f(bit);
        }
        // Install next state into the OTHER copy: no barrier needed here;
        // readers sync on the next iteration's top __syncthreads().
        nxt[(8 + w) * 32 + lane] = sw2;
    }
}

extern "C" void kernel_launch(void* const* d_in, const int* in_sizes, int n_in,
                              void* d_out, int out_size) {
    const float* inp        = (const float*)d_in[0];  // [128,256,256] bool->f32
    const float* init_state = (const float*)d_in[1];  // [256,256] bool->f32
    const int*   connA      = (const int*)d_in[2];    // [1024,16] int32
    const float* memA       = (const float*)d_in[3];  // [1024,65536] bool->f32
    const int*   connB      = (const int*)d_in[4];    // [256,16] int32
    const float* memB       = (const float*)d_in[5];  // [256,65536] bool->f32
    float* out = (float*)d_out;
    (void)in_sizes; (void)n_in; (void)out_size;

    uint32_t *p_inp, *p_memA, *p_memB, *p_connA, *p_connB;
    cudaGetSymbolAddress((void**)&p_inp,   g_inp);
    cudaGetSymbolAddress((void**)&p_memA,  g_memA);
    cudaGetSymbolAddress((void**)&p_memB,  g_memB);
    cudaGetSymbolAddress((void**)&p_connA, g_connA);
    cudaGetSymbolAddress((void**)&p_connB, g_connB);

    // precompute: bit-pack inputs/tables, pre-decode connections
    {
        int nw = SEQ * BATCH * 8;               // 262144
        pack_f32_kernel<<<(nw + 255) / 256, 256>>>(inp, p_inp, nw);
    }
    {
        int nw = N_IN * 2048;                   // 2097152
        pack_f32_kernel<<<(nw + 255) / 256, 256>>>(memA, p_memA, nw);
    }
    {
        int nw = N_ST * 2048;                   // 524288
        pack_f32_kernel<<<(nw + 255) / 256, 256>>>(memB, p_memB, nw);
    }
    pack_connA_kernel<<<(N_IN * 16 + 255) / 256, 256>>>(connA, p_connA, N_IN * 16);
    pack_connB_kernel<<<(N_ST * 16 + 255) / 256, 256>>>(connB, p_connB, N_ST * 16);

    // main recurrence: 256 blocks, one independent batch chain each
    ram_main<<<BATCH, 256>>>(init_state, out);
}

// round 13
// speedup vs baseline: 1.0249x; 1.0249x over previous
#include <cuda_runtime.h>
#include <cstdint>

#define SEQ 128
#define BATCH 256
#define N_IN 1024
#define N_ST 256

// ---------------- static device scratch (no allocations allowed) ----------------
__device__ uint32_t g_inp[SEQ * BATCH * 8];     // packed input bits: [t][b][8 words]
__device__ uint32_t g_memA[N_IN * 2048];        // packed input-layer RAM: [n][2048 words]
__device__ uint32_t g_memB[N_ST * 2048];        // packed state-layer RAM
__device__ uint32_t g_connA[N_IN * 16];         // (shift<<16) | (row_word_offset)
__device__ uint32_t g_connB[N_ST * 16];

#define NW_INP  (SEQ * BATCH * 8)       // 262144
#define NW_MEMA (N_IN * 2048)           // 2097152
#define NW_MEMB (N_ST * 2048)           // 524288
#define NW_ALL  (NW_INP + NW_MEMA + NW_MEMB)

// Pack 32 float32 {0.0,1.0} -> one word, for all three bool tensors in one grid.
__global__ void pack_all_kernel(const float* __restrict__ inp,
                                const float* __restrict__ memA,
                                const float* __restrict__ memB,
                                uint32_t* __restrict__ d_inp,
                                uint32_t* __restrict__ d_memA,
                                uint32_t* __restrict__ d_memB) {
    int i = blockIdx.x * blockDim.x + threadIdx.x;
    const float* src; uint32_t* dst; int j;
    if (i < NW_INP)                 { src = inp;  dst = d_inp;  j = i; }
    else if (i < NW_INP + NW_MEMA)  { src = memA; dst = d_memA; j = i - NW_INP; }
    else if (i < NW_ALL)            { src = memB; dst = d_memB; j = i - NW_INP - NW_MEMA; }
    else return;
    const uint4* q = (const uint4*)(src + (size_t)j * 32);
    uint32_t r = 0;
#pragma unroll
    for (int k = 0; k < 8; ++k) {
        uint4 x = q[k];
        r |= (x.x ? 1u : 0u) << (k * 4 + 0);
        r |= (x.y ? 1u : 0u) << (k * 4 + 1);
        r |= (x.z ? 1u : 0u) << (k * 4 + 2);
        r |= (x.w ? 1u : 0u) << (k * 4 + 3);
    }
    dst[j] = r;
}

// Unified layout U (48 rows x 32 lanes): rows 0-7 inp, 8-15 state, 16-47 io.
// connA p in [0,512): row = p>>5.  connB p in [0,1280): io -> 16+(p>>5),
// state (p>=1024) -> (p>>5)-24.  Encoded as (shift<<16) | row*32.
__global__ void pack_conn_all_kernel(const int* __restrict__ connA,
                                     const int* __restrict__ connB,
                                     uint32_t* __restrict__ dA,
                                     uint32_t* __restrict__ dB) {
    int i = blockIdx.x * blockDim.x + threadIdx.x;
    if (i < N_IN * 16) {
        uint32_t v = (uint32_t)connA[i];
        dA[i] = ((v & 31u) << 16) | ((v >> 5) * 32u);
    } else if (i < N_IN * 16 + N_ST * 16) {
        int j = i - N_IN * 16;
        uint32_t v = (uint32_t)connB[j];
        uint32_t row = (v < 1024u) ? (16u + (v >> 5)) : ((v >> 5) - 24u);
        dB[j] = ((v & 31u) << 16) | (row * 32u);
    }
}

// ---------------- main recurrent kernel ----------------
__device__ __forceinline__ uint32_t gstep(uint32_t a, uint32_t c,
                                          const uint32_t* __restrict__ rep, int lane) {
    uint32_t w = rep[(c & 0xffffu) + lane];
    return (a + a) | ((w >> (c >> 16)) & 1u);
}

__device__ __forceinline__ uint32_t gather16(const uint32_t* __restrict__ cw,
                                             const uint32_t* __restrict__ rep, int lane) {
    uint32_t a = 0;
#pragma unroll
    for (int k = 15; k >= 0; --k) a = gstep(a, cw[k], rep, lane);
    return a;
}

__device__ __forceinline__ float bit2f(uint32_t bit) {
    return __uint_as_float(0x3F800000u & (0u - bit));   // 1.0f / 0.0f, pure ALU
}

__global__ __launch_bounds__(256, 2)
void ram_main(const float* __restrict__ init_state, float* __restrict__ out) {
    // Ping-ponged lane-replicated bit vectors (bank == lane -> conflict-free).
    __shared__ uint32_t U[2][48 * 32];

    const int tid  = threadIdx.x;
    const int lane = tid & 31;
    const int w    = tid >> 5;          // warp 0..7
    const int b    = blockIdx.x;        // one batch per block

    // Hoist loop-invariant connections into registers (64 + 16 words).
    uint32_t cA[64], cB[16];
#pragma unroll
    for (int gi = 0; gi < 4; ++gi) {
        int n = (w * 4 + gi) * 32 + lane;
#pragma unroll
        for (int k = 0; k < 16; ++k) cA[gi * 16 + k] = g_connA[n * 16 + k];
    }
#pragma unroll
    for (int k = 0; k < 16; ++k) cB[k] = g_connB[(w * 32 + lane) * 16 + k];

    // Hoist loop-invariant base pointers (table rows, input, output).
    const uint32_t* tabA0 = g_memA + (size_t)((w * 4 + 0) * 32 + lane) * 2048;
    const uint32_t* tabA1 = g_memA + (size_t)((w * 4 + 1) * 32 + lane) * 2048;
    const uint32_t* tabA2 = g_memA + (size_t)((w * 4 + 2) * 32 + lane) * 2048;
    const uint32_t* tabA3 = g_memA + (size_t)((w * 4 + 3) * 32 + lane) * 2048;
    const uint32_t* tabB  = g_memB + (size_t)(w * 32 + lane) * 2048;
    const uint32_t* ginp  = g_inp + (size_t)b * 8 + w;
    float*          outp  = out + (size_t)b * N_IN + w * 128 + lane;

    // Pre-load step 0: init state + input into copy 0.
    {
        float f = init_state[b * N_ST + w * 32 + lane];
        uint32_t word = __ballot_sync(0xffffffffu, f != 0.0f);
        U[0][(8 + w) * 32 + lane] = word;
        U[0][w * 32 + lane] = __ldg(ginp);
    }

    for (int t = 0; t < SEQ; ++t) {
        uint32_t* cur = U[t & 1];
        uint32_t* nxt = U[(t + 1) & 1];

        __syncthreads();   // prev state install + prefetched input visible

        // Prefetch next step's input (stored later, off the critical path).
        uint32_t pin = 0;
        if (t + 1 < SEQ) pin = __ldg(ginp + (size_t)(t + 1) * BATCH * 8);

        // ---- phase A: all 4 gathers batched, then all 4 table LDGs batched ----
        uint32_t acc[4], tw[4];
#pragma unroll
        for (int gi = 0; gi < 4; ++gi)
            acc[gi] = gather16(&cA[gi * 16], cur, lane);
        tw[0] = __ldcg(tabA0 + (acc[0] >> 5));
        tw[1] = __ldcg(tabA1 + (acc[1] >> 5));
        tw[2] = __ldcg(tabA2 + (acc[2] >> 5));
        tw[3] = __ldcg(tabA3 + (acc[3] >> 5));

        if (t + 1 < SEQ) nxt[w * 32 + lane] = pin;   // hidden behind table LDGs

#pragma unroll
        for (int gi = 0; gi < 4; ++gi) {
            uint32_t bit = (tw[gi] >> (acc[gi] & 31u)) & 1u;
            uint32_t iow = __ballot_sync(0xffffffffu, bit != 0u);
            cur[(16 + w * 4 + gi) * 32 + lane] = iow;   // replicate io word
            outp[gi * 32] = bit2f(bit);                 // coalesced 128B store
        }
        __syncthreads();   // io words visible

        // ---- phase B: 256 neurons; warp w handles neurons w*32 .. w*32+31 ----
        uint32_t a   = gather16(cB, cur, lane);
        uint32_t twb = __ldcg(tabB + (a >> 5));
        uint32_t bit = (twb >> (a & 31u)) & 1u;
        uint32_t sw2 = __ballot_sync(0xffffffffu, bit != 0u);

        if (t == SEQ - 1) {
            out[(size_t)SEQ * BATCH * N_IN + b * N_ST + w * 32 + lane] = bit2f(bit);
        }
        // Install next state into the OTHER copy; readers sync at next top barrier.
        nxt[(8 + w) * 32 + lane] = sw2;

        outp += (size_t)BATCH * N_IN;
    }
}

extern "C" void kernel_launch(void* const* d_in, const int* in_sizes, int n_in,
                              void* d_out, int out_size) {
    const float* inp        = (const float*)d_in[0];  // [128,256,256] bool->f32
    const float* init_state = (const float*)d_in[1];  // [256,256] bool->f32
    const int*   connA      = (const int*)d_in[2];    // [1024,16] int32
    const float* memA       = (const float*)d_in[3];  // [1024,65536] bool->f32
    const int*   connB      = (const int*)d_in[4];    // [256,16] int32
    const float* memB       = (const float*)d_in[5];  // [256,65536] bool->f32
    float* out = (float*)d_out;
    (void)in_sizes; (void)n_in; (void)out_size;

    uint32_t *p_inp, *p_memA, *p_memB, *p_connA, *p_connB;
    cudaGetSymbolAddress((void**)&p_inp,   g_inp);
    cudaGetSymbolAddress((void**)&p_memA,  g_memA);
    cudaGetSymbolAddress((void**)&p_memB,  g_memB);
    cudaGetSymbolAddress((void**)&p_connA, g_connA);
    cudaGetSymbolAddress((void**)&p_connB, g_connB);

    // precompute: one fused bit-pack pass + one fused conn-decode pass
    pack_all_kernel<<<(NW_ALL + 255) / 256, 256>>>(inp, memA, memB,
                                                   p_inp, p_memA, p_memB);
    pack_conn_all_kernel<<<((N_IN + N_ST) * 16 + 255) / 256, 256>>>(
        connA, connB, p_connA, p_connB);

    // main recurrence: 256 blocks, one independent batch chain each
    ram_main<<<BATCH, 256>>>(init_state, out);
}